// round 1
// baseline (speedup 1.0000x reference)
#include <cuda_runtime.h>
#include <math.h>

// Problem constants (fixed by the dataset)
#define NN  50000
#define EE  800000
#define FIN 128
#define HH  128
#define CC  64

// ---------------- device scratch (allocation-free rule: __device__ globals) ---
__device__ float g_cnt [NN];
__device__ float g_inv [NN];
__device__ float g_sum1[NN * FIN];   // scatter target, layer 1 (x features)
__device__ float g_h   [NN * HH];    // relu(norm(sage1))
__device__ float g_h2  [NN * HH];    // relu([x,h] @ Wl1^T + bl1)
__device__ float g_t2  [NN * CC];    // h2 @ W2_l^T   (pre-transformed for aggregation)
__device__ float g_r2  [NN * CC];    // h2 @ W2_r^T
__device__ float g_sum2[NN * CC];    // scatter target, layer 2 (t2 features)

// ---------------- init: zero scatter buffers + degree counts ------------------
__global__ void k_init() {
    int i = blockIdx.x * blockDim.x + threadIdx.x;
    if (i < NN * FIN) g_sum1[i] = 0.f;
    if (i < NN * CC)  g_sum2[i] = 0.f;
    if (i < NN)       g_cnt[i]  = 0.f;
}

// ---------------- degree count -------------------------------------------------
__global__ void k_count(const int* __restrict__ ei) {
    int e = blockIdx.x * blockDim.x + threadIdx.x;
    if (e < EE) {
        int dst = ei[EE + e];
        atomicAdd(&g_cnt[dst], 1.0f);
    }
}

__global__ void k_invcnt() {
    int n = blockIdx.x * blockDim.x + threadIdx.x;
    if (n < NN) g_inv[n] = 1.0f / fmaxf(g_cnt[n], 1.0f);
}

// ---------------- vector f32 reduction helper ----------------------------------
__device__ __forceinline__ void red_add_v4(float* p, float4 v) {
    asm volatile("red.global.add.v4.f32 [%0], {%1,%2,%3,%4};"
                 :: "l"(p), "f"(v.x), "f"(v.y), "f"(v.z), "f"(v.w) : "memory");
}

// ---------------- scatter 1: sum1[dst] += x[src], 128 floats, 1 warp/edge ------
__global__ void k_scatter1(const int* __restrict__ ei, const float* __restrict__ x) {
    int gw   = (blockIdx.x * blockDim.x + threadIdx.x) >> 5;
    int lane = threadIdx.x & 31;
    if (gw >= EE) return;
    int src = ei[gw];
    int dst = ei[EE + gw];
    float4 v = ((const float4*)(x + (size_t)src * FIN))[lane];
    red_add_v4(g_sum1 + (size_t)dst * FIN + lane * 4, v);
}

// ---------------- scatter 2: sum2[dst] += t2[src], 64 floats, 2 edges/warp -----
__global__ void k_scatter2(const int* __restrict__ ei) {
    int gw   = (blockIdx.x * blockDim.x + threadIdx.x) >> 5;
    int lane = threadIdx.x & 31;
    int e    = gw * 2 + (lane >> 4);
    if (e >= EE) return;
    int l   = lane & 15;
    int src = ei[e];
    int dst = ei[EE + e];
    float4 v = ((const float4*)(g_t2 + (size_t)src * CC))[l];
    red_add_v4(g_sum2 + (size_t)dst * CC + l * 4, v);
}

// ---------------- fused tall-skinny SGEMM, BM=128 x BJ=128, 8x8/thread ---------
// MODE 0: out = norm_relu( concat(agg1, x) @ [W1_l|W1_r]^T + b1 ) -> g_h
// MODE 1: g_h2 = relu( concat(x, h) @ Wl1^T + bl1 )
// MODE 2: [g_t2|g_r2] = g_h2 @ [W2_l ; W2_r]^T          (K=128, no bias here)
template <int MODE>
__launch_bounds__(256)
__global__ void k_gemm(const float* __restrict__ X,
                       const float* __restrict__ WA,
                       const float* __restrict__ WB,
                       const float* __restrict__ bias) {
    constexpr int KTOT = (MODE == 2) ? 128 : 256;
    constexpr int BK = 32, PAD = 132;
    __shared__ float As[BK * PAD];
    __shared__ float Ws[BK * PAD];

    const int tid = threadIdx.x;
    const int tx  = tid & 15;    // channel group (8 channels each)
    const int ty  = tid >> 4;    // node group    (8 nodes each)
    const int m0  = blockIdx.x * 128;

    float acc[8][8];
#pragma unroll
    for (int i = 0; i < 8; i++)
#pragma unroll
        for (int j = 0; j < 8; j++) acc[i][j] = 0.f;

    for (int k0 = 0; k0 < KTOT; k0 += BK) {
        // --- load A chunk, transposed into As[k][node] ---
#pragma unroll
        for (int p = 0; p < 4; p++) {
            int f4 = tid + p * 256;     // 0..1023
            int n  = f4 >> 3;           // node 0..127
            int kq = f4 & 7;            // float4 within BK
            int k  = k0 + kq * 4;
            int gm = m0 + n;
            float4 v = make_float4(0.f, 0.f, 0.f, 0.f);
            if (gm < NN) {
                if (MODE == 0) {
                    if (k < 128) {
                        v = *(const float4*)(g_sum1 + (size_t)gm * 128 + k);
                        float s = g_inv[gm];
                        v.x *= s; v.y *= s; v.z *= s; v.w *= s;
                    } else {
                        v = *(const float4*)(X + (size_t)gm * 128 + (k - 128));
                    }
                } else if (MODE == 1) {
                    if (k < 128) v = *(const float4*)(X   + (size_t)gm * 128 + k);
                    else         v = *(const float4*)(g_h + (size_t)gm * 128 + (k - 128));
                } else {
                    v = *(const float4*)(g_h2 + (size_t)gm * 128 + k);
                }
            }
            int kk = kq * 4;
            As[(kk + 0) * PAD + n] = v.x;
            As[(kk + 1) * PAD + n] = v.y;
            As[(kk + 2) * PAD + n] = v.z;
            As[(kk + 3) * PAD + n] = v.w;
        }
        // --- load W chunk, transposed into Ws[k][j] ---
#pragma unroll
        for (int p = 0; p < 4; p++) {
            int f4 = tid + p * 256;
            int j  = f4 >> 3;           // out-channel 0..127
            int kq = f4 & 7;
            int k  = k0 + kq * 4;
            float4 v;
            if (MODE == 0) {
                v = (k < 128) ? *(const float4*)(WA + j * 128 + k)
                              : *(const float4*)(WB + j * 128 + (k - 128));
            } else if (MODE == 1) {
                v = *(const float4*)(WA + j * 256 + k);
            } else {
                v = (j < 64) ? *(const float4*)(WA + j * 128 + k)
                             : *(const float4*)(WB + (j - 64) * 128 + k);
            }
            int kk = kq * 4;
            Ws[(kk + 0) * PAD + j] = v.x;
            Ws[(kk + 1) * PAD + j] = v.y;
            Ws[(kk + 2) * PAD + j] = v.z;
            Ws[(kk + 3) * PAD + j] = v.w;
        }
        __syncthreads();

#pragma unroll 4
        for (int kk = 0; kk < BK; kk++) {
            float4 a0 = *(const float4*)(As + kk * PAD + ty * 8);
            float4 a1 = *(const float4*)(As + kk * PAD + ty * 8 + 4);
            float4 w0 = *(const float4*)(Ws + kk * PAD + tx * 8);
            float4 w1 = *(const float4*)(Ws + kk * PAD + tx * 8 + 4);
            float a[8] = {a0.x, a0.y, a0.z, a0.w, a1.x, a1.y, a1.z, a1.w};
            float w[8] = {w0.x, w0.y, w0.z, w0.w, w1.x, w1.y, w1.z, w1.w};
#pragma unroll
            for (int i = 0; i < 8; i++)
#pragma unroll
                for (int j = 0; j < 8; j++) acc[i][j] += a[i] * w[j];
        }
        __syncthreads();
    }

    const int cbase = tx * 8;

    if (MODE == 0 || MODE == 1) {
        float bv[8];
#pragma unroll
        for (int j = 0; j < 8; j++) bv[j] = bias[cbase + j];
#pragma unroll
        for (int i = 0; i < 8; i++)
#pragma unroll
            for (int j = 0; j < 8; j++) acc[i][j] += bv[j];
    }

    if (MODE == 0) {
        // L2 row-norm over 128 channels (spread over 16 tx lanes), then relu.
#pragma unroll
        for (int i = 0; i < 8; i++) {
            float ss = 0.f;
#pragma unroll
            for (int j = 0; j < 8; j++) ss += acc[i][j] * acc[i][j];
#pragma unroll
            for (int o = 1; o < 16; o <<= 1) ss += __shfl_xor_sync(0xffffffffu, ss, o);
            float s = 1.0f / fmaxf(sqrtf(ss), 1e-12f);
            int gm = m0 + ty * 8 + i;
            if (gm < NN) {
                float4 o0, o1;
                o0.x = fmaxf(acc[i][0] * s, 0.f); o0.y = fmaxf(acc[i][1] * s, 0.f);
                o0.z = fmaxf(acc[i][2] * s, 0.f); o0.w = fmaxf(acc[i][3] * s, 0.f);
                o1.x = fmaxf(acc[i][4] * s, 0.f); o1.y = fmaxf(acc[i][5] * s, 0.f);
                o1.z = fmaxf(acc[i][6] * s, 0.f); o1.w = fmaxf(acc[i][7] * s, 0.f);
                *(float4*)(g_h + (size_t)gm * 128 + cbase)     = o0;
                *(float4*)(g_h + (size_t)gm * 128 + cbase + 4) = o1;
            }
        }
    } else if (MODE == 1) {
#pragma unroll
        for (int i = 0; i < 8; i++) {
            int gm = m0 + ty * 8 + i;
            if (gm < NN) {
                float4 o0, o1;
                o0.x = fmaxf(acc[i][0], 0.f); o0.y = fmaxf(acc[i][1], 0.f);
                o0.z = fmaxf(acc[i][2], 0.f); o0.w = fmaxf(acc[i][3], 0.f);
                o1.x = fmaxf(acc[i][4], 0.f); o1.y = fmaxf(acc[i][5], 0.f);
                o1.z = fmaxf(acc[i][6], 0.f); o1.w = fmaxf(acc[i][7], 0.f);
                *(float4*)(g_h2 + (size_t)gm * 128 + cbase)     = o0;
                *(float4*)(g_h2 + (size_t)gm * 128 + cbase + 4) = o1;
            }
        }
    } else {
        // channels 0..63 -> t2, 64..127 -> r2 (each thread's 8 channels are on one side)
        float* dstbuf = (cbase < 64) ? g_t2 : g_r2;
        int     coff  = (cbase < 64) ? cbase : (cbase - 64);
#pragma unroll
        for (int i = 0; i < 8; i++) {
            int gm = m0 + ty * 8 + i;
            if (gm < NN) {
                float4 o0 = make_float4(acc[i][0], acc[i][1], acc[i][2], acc[i][3]);
                float4 o1 = make_float4(acc[i][4], acc[i][5], acc[i][6], acc[i][7]);
                *(float4*)(dstbuf + (size_t)gm * 64 + coff)     = o0;
                *(float4*)(dstbuf + (size_t)gm * 64 + coff + 4) = o1;
            }
        }
    }
}

// ---------------- final: out = norm( sum2/cnt + b2 + r2 ), 1 warp/node ---------
__global__ void k_out(const float* __restrict__ b2, float* __restrict__ out) {
    int node = (blockIdx.x * blockDim.x + threadIdx.x) >> 5;
    int lane = threadIdx.x & 31;
    if (node >= NN) return;
    float inv = g_inv[node];
    float2 s  = ((const float2*)(g_sum2 + (size_t)node * CC))[lane];
    float2 r  = ((const float2*)(g_r2   + (size_t)node * CC))[lane];
    float2 bb = ((const float2*)b2)[lane];
    float v0 = s.x * inv + bb.x + r.x;
    float v1 = s.y * inv + bb.y + r.y;
    float ss = v0 * v0 + v1 * v1;
#pragma unroll
    for (int o = 16; o >= 1; o >>= 1) ss += __shfl_xor_sync(0xffffffffu, ss, o);
    float sc = 1.0f / fmaxf(sqrtf(ss), 1e-12f);
    float2 o2 = make_float2(v0 * sc, v1 * sc);
    ((float2*)(out + (size_t)node * CC))[lane] = o2;
}

// ---------------- launch --------------------------------------------------------
extern "C" void kernel_launch(void* const* d_in, const int* in_sizes, int n_in,
                              void* d_out, int out_size) {
    const float* x    = (const float*)d_in[0];
    const int*   ei   = (const int*)  d_in[1];
    const float* W1_l = (const float*)d_in[2];
    const float* b1   = (const float*)d_in[3];
    const float* W1_r = (const float*)d_in[4];
    const float* Wl1  = (const float*)d_in[5];
    const float* bl1  = (const float*)d_in[6];
    const float* W2_l = (const float*)d_in[7];
    const float* b2   = (const float*)d_in[8];
    const float* W2_r = (const float*)d_in[9];
    float* out = (float*)d_out;

    k_init  <<<(NN * FIN + 255) / 256, 256>>>();
    k_count <<<(EE + 255) / 256, 256>>>(ei);
    k_invcnt<<<(NN + 255) / 256, 256>>>();
    k_scatter1<<<(EE * 32 + 255) / 256, 256>>>(ei, x);
    k_gemm<0><<<(NN + 127) / 128, 256>>>(x, W1_l, W1_r, b1);
    k_gemm<1><<<(NN + 127) / 128, 256>>>(x, Wl1, (const float*)nullptr, bl1);
    k_gemm<2><<<(NN + 127) / 128, 256>>>((const float*)nullptr, W2_l, W2_r, (const float*)nullptr);
    k_scatter2<<<(EE * 16 + 255) / 256, 256>>>(ei);
    k_out<<<(NN * 32 + 255) / 256, 256>>>(b2, out);
}

// round 2
// speedup vs baseline: 1.3396x; 1.3396x over previous
#include <cuda_runtime.h>
#include <math.h>

// Problem constants (fixed by the dataset)
#define NN  50000
#define EE  800000
#define FIN 128
#define HH  128
#define CC  64

// ---------------- device scratch ------------------------------------------------
__device__ float g_cnt [NN];
__device__ float g_inv [NN];
__device__ float g_sum1[NN * FIN];   // scatter target, layer 1 (x features)
__device__ float g_h   [NN * HH];    // relu(norm(sage1))
__device__ float g_h2  [NN * HH];    // relu([x,h] @ Wl1^T + bl1)
__device__ float g_t2  [NN * CC];    // h2 @ W2_l^T (pre-transformed; aggregated by linearity)
__device__ float g_r2  [NN * CC];    // h2 @ W2_r^T
__device__ float g_sum2[NN * CC];    // scatter target, layer 2 (t2 features)

// ---------------- init ----------------------------------------------------------
__global__ void k_init() {
    int i = blockIdx.x * blockDim.x + threadIdx.x;
    if (i < NN * FIN) g_sum1[i] = 0.f;
    if (i < NN * CC)  g_sum2[i] = 0.f;
    if (i < NN)       g_cnt[i]  = 0.f;
}

__global__ void k_count(const int* __restrict__ ei) {
    int e = blockIdx.x * blockDim.x + threadIdx.x;
    if (e < EE) atomicAdd(&g_cnt[ei[EE + e]], 1.0f);
}

__global__ void k_invcnt() {
    int n = blockIdx.x * blockDim.x + threadIdx.x;
    if (n < NN) g_inv[n] = 1.0f / fmaxf(g_cnt[n], 1.0f);
}

// ---------------- vector f32 reduction helper -----------------------------------
__device__ __forceinline__ void red_add_v4(float* p, float4 v) {
    asm volatile("red.global.add.v4.f32 [%0], {%1,%2,%3,%4};"
                 :: "l"(p), "f"(v.x), "f"(v.y), "f"(v.z), "f"(v.w) : "memory");
}

// ---------------- scatter 1: sum1[dst] += x[src], 1 warp/edge --------------------
__global__ void k_scatter1(const int* __restrict__ ei, const float* __restrict__ x) {
    int gw   = (blockIdx.x * blockDim.x + threadIdx.x) >> 5;
    int lane = threadIdx.x & 31;
    if (gw >= EE) return;
    int src = ei[gw];
    int dst = ei[EE + gw];
    float4 v = ((const float4*)(x + (size_t)src * FIN))[lane];
    red_add_v4(g_sum1 + (size_t)dst * FIN + lane * 4, v);
}

// ---------------- scatter 2: sum2[dst] += t2[src], 2 edges/warp ------------------
__global__ void k_scatter2(const int* __restrict__ ei) {
    int gw   = (blockIdx.x * blockDim.x + threadIdx.x) >> 5;
    int lane = threadIdx.x & 31;
    int e    = gw * 2 + (lane >> 4);
    if (e >= EE) return;
    int l   = lane & 15;
    int src = ei[e];
    int dst = ei[EE + e];
    float4 v = ((const float4*)(g_t2 + (size_t)src * CC))[l];
    red_add_v4(g_sum2 + (size_t)dst * CC + l * 4, v);
}

// ---------------- tf32 helpers ----------------------------------------------------
__device__ __forceinline__ unsigned f2tf32(float f) {
    unsigned r;
    asm("cvt.rna.tf32.f32 %0, %1;" : "=r"(r) : "f"(f));
    return r;
}

#define MMA_TF32(d, a, b)                                                       \
    asm volatile("mma.sync.aligned.m16n8k8.row.col.f32.tf32.tf32.f32 "          \
                 "{%0,%1,%2,%3}, {%4,%5,%6,%7}, {%8,%9}, {%0,%1,%2,%3};"        \
                 : "+f"(d[0]), "+f"(d[1]), "+f"(d[2]), "+f"(d[3])               \
                 : "r"(a[0]), "r"(a[1]), "r"(a[2]), "r"(a[3]),                  \
                   "r"(b[0]), "r"(b[1]))

// ---------------- tensor-core tf32 SGEMM, 128x128 tile, 8 warps ------------------
// MODE 0: g_h  = relu( norm( [sum1*inv | x] @ [W1_l|W1_r]^T + b1 ) )   K=256
// MODE 1: g_h2 = relu( [x | h] @ Wl1^T + bl1 )                         K=256
// MODE 2: [g_t2|g_r2] = g_h2 @ [W2_l ; W2_r]^T                         K=128
#define SAS 136   // smem row stride (words); 136 % 32 == 8 -> conflict-free frags

template <int MODE>
__launch_bounds__(256)
__global__ void k_gemm(const float* __restrict__ X,
                       const float* __restrict__ WA,
                       const float* __restrict__ WB,
                       const float* __restrict__ bias) {
    constexpr int KTOT = (MODE == 2) ? 128 : 256;
    __shared__ unsigned As[32 * SAS];
    __shared__ unsigned Ws[32 * SAS];
    __shared__ float    rss[128 * 4];   // MODE 0 cross-warp row-norm partials

    const int tid  = threadIdx.x;
    const int lane = tid & 31;
    const int w    = tid >> 5;
    const int wm   = w & 1;        // 0..1   (64 rows each)
    const int wn   = w >> 1;       // 0..3   (32 cols each)
    const int qid  = lane >> 2;    // 0..7
    const int tig  = lane & 3;     // 0..3
    const int m0   = blockIdx.x * 128;

    float acc[4][4][4];
#pragma unroll
    for (int mt = 0; mt < 4; mt++)
#pragma unroll
        for (int nt = 0; nt < 4; nt++)
#pragma unroll
            for (int c = 0; c < 4; c++) acc[mt][nt][c] = 0.f;

    for (int k0 = 0; k0 < KTOT; k0 += 32) {
        // ---- A tile: 128 rows x 32 k, k-major into As[k][m] ----
#pragma unroll
        for (int p = 0; p < 4; p++) {
            int f4 = tid + p * 256;       // 0..1023
            int n  = f4 >> 3;             // node 0..127
            int kq = f4 & 7;
            int k  = k0 + kq * 4;
            int gm = m0 + n;
            float4 v = make_float4(0.f, 0.f, 0.f, 0.f);
            if (gm < NN) {
                if (MODE == 0) {
                    if (k < 128) {
                        v = *(const float4*)(g_sum1 + (size_t)gm * 128 + k);
                        float s = g_inv[gm];
                        v.x *= s; v.y *= s; v.z *= s; v.w *= s;
                    } else {
                        v = *(const float4*)(X + (size_t)gm * 128 + (k - 128));
                    }
                } else if (MODE == 1) {
                    if (k < 128) v = *(const float4*)(X   + (size_t)gm * 128 + k);
                    else         v = *(const float4*)(g_h + (size_t)gm * 128 + (k - 128));
                } else {
                    v = *(const float4*)(g_h2 + (size_t)gm * 128 + k);
                }
            }
            int kk = kq * 4;
            As[(kk + 0) * SAS + n] = f2tf32(v.x);
            As[(kk + 1) * SAS + n] = f2tf32(v.y);
            As[(kk + 2) * SAS + n] = f2tf32(v.z);
            As[(kk + 3) * SAS + n] = f2tf32(v.w);
        }
        // ---- W tile: 128 out-channels x 32 k, k-major into Ws[k][j] ----
#pragma unroll
        for (int p = 0; p < 4; p++) {
            int f4 = tid + p * 256;
            int j  = f4 >> 3;
            int kq = f4 & 7;
            int k  = k0 + kq * 4;
            float4 v;
            if (MODE == 0) {
                v = (k < 128) ? *(const float4*)(WA + j * 128 + k)
                              : *(const float4*)(WB + j * 128 + (k - 128));
            } else if (MODE == 1) {
                v = *(const float4*)(WA + j * 256 + k);
            } else {
                v = (j < 64) ? *(const float4*)(WA + j * 128 + k)
                             : *(const float4*)(WB + (j - 64) * 128 + k);
            }
            int kk = kq * 4;
            Ws[(kk + 0) * SAS + j] = f2tf32(v.x);
            Ws[(kk + 1) * SAS + j] = f2tf32(v.y);
            Ws[(kk + 2) * SAS + j] = f2tf32(v.z);
            Ws[(kk + 3) * SAS + j] = f2tf32(v.w);
        }
        __syncthreads();

#pragma unroll
        for (int ks = 0; ks < 4; ks++) {
            const int kr = ks * 8 + tig;
            unsigned a[4][4];
#pragma unroll
            for (int mt = 0; mt < 4; mt++) {
                int r0 = wm * 64 + mt * 16 + qid;
                a[mt][0] = As[kr * SAS + r0];
                a[mt][1] = As[kr * SAS + r0 + 8];
                a[mt][2] = As[(kr + 4) * SAS + r0];
                a[mt][3] = As[(kr + 4) * SAS + r0 + 8];
            }
            unsigned b[4][2];
#pragma unroll
            for (int nt = 0; nt < 4; nt++) {
                int c0 = wn * 32 + nt * 8 + qid;
                b[nt][0] = Ws[kr * SAS + c0];
                b[nt][1] = Ws[(kr + 4) * SAS + c0];
            }
#pragma unroll
            for (int mt = 0; mt < 4; mt++)
#pragma unroll
                for (int nt = 0; nt < 4; nt++)
                    MMA_TF32(acc[mt][nt], a[mt], b[nt]);
        }
        __syncthreads();
    }

    // ---------------- epilogue ----------------
    // row(c) = wm*64 + mt*16 + qid + (c>=2 ? 8 : 0)
    // col(c) = wn*32 + nt*8 + tig*2 + (c&1)

    if (MODE == 0 || MODE == 1) {
        // add bias
#pragma unroll
        for (int nt = 0; nt < 4; nt++) {
            float2 bv = *(const float2*)(bias + wn * 32 + nt * 8 + tig * 2);
#pragma unroll
            for (int mt = 0; mt < 4; mt++) {
                acc[mt][nt][0] += bv.x; acc[mt][nt][1] += bv.y;
                acc[mt][nt][2] += bv.x; acc[mt][nt][3] += bv.y;
            }
        }
    }

    if (MODE == 0) {
        // per-row L2 norm across all 128 channels, then relu, store g_h
        // partials per (mt, half) within this warp's 32 columns:
        float ssl[4][2];
#pragma unroll
        for (int mt = 0; mt < 4; mt++) {
            float s0 = 0.f, s1 = 0.f;
#pragma unroll
            for (int nt = 0; nt < 4; nt++) {
                s0 += acc[mt][nt][0] * acc[mt][nt][0] + acc[mt][nt][1] * acc[mt][nt][1];
                s1 += acc[mt][nt][2] * acc[mt][nt][2] + acc[mt][nt][3] * acc[mt][nt][3];
            }
            // reduce over the 4 lanes of the quad (same row, different tig)
            s0 += __shfl_xor_sync(0xffffffffu, s0, 1);
            s0 += __shfl_xor_sync(0xffffffffu, s0, 2);
            s1 += __shfl_xor_sync(0xffffffffu, s1, 1);
            s1 += __shfl_xor_sync(0xffffffffu, s1, 2);
            ssl[mt][0] = s0; ssl[mt][1] = s1;
        }
        // cross-warp (4 wn warps share rows)
        if (tig == 0) {
#pragma unroll
            for (int mt = 0; mt < 4; mt++) {
                int r0 = wm * 64 + mt * 16 + qid;
                rss[(r0)     * 4 + wn] = ssl[mt][0];
                rss[(r0 + 8) * 4 + wn] = ssl[mt][1];
            }
        }
        __syncthreads();
#pragma unroll
        for (int mt = 0; mt < 4; mt++) {
#pragma unroll
            for (int h = 0; h < 2; h++) {
                int r = wm * 64 + mt * 16 + qid + h * 8;
                float ss = rss[r * 4 + 0] + rss[r * 4 + 1] + rss[r * 4 + 2] + rss[r * 4 + 3];
                float sc = 1.0f / fmaxf(sqrtf(ss), 1e-12f);
                int gm = m0 + r;
                if (gm < NN) {
#pragma unroll
                    for (int nt = 0; nt < 4; nt++) {
                        float2 o;
                        o.x = fmaxf(acc[mt][nt][h * 2 + 0] * sc, 0.f);
                        o.y = fmaxf(acc[mt][nt][h * 2 + 1] * sc, 0.f);
                        *(float2*)(g_h + (size_t)gm * 128 + wn * 32 + nt * 8 + tig * 2) = o;
                    }
                }
            }
        }
    } else if (MODE == 1) {
#pragma unroll
        for (int mt = 0; mt < 4; mt++) {
#pragma unroll
            for (int h = 0; h < 2; h++) {
                int gm = m0 + wm * 64 + mt * 16 + qid + h * 8;
                if (gm < NN) {
#pragma unroll
                    for (int nt = 0; nt < 4; nt++) {
                        float2 o;
                        o.x = fmaxf(acc[mt][nt][h * 2 + 0], 0.f);
                        o.y = fmaxf(acc[mt][nt][h * 2 + 1], 0.f);
                        *(float2*)(g_h2 + (size_t)gm * 128 + wn * 32 + nt * 8 + tig * 2) = o;
                    }
                }
            }
        }
    } else {
        float* dstbuf = (wn < 2) ? g_t2 : g_r2;
        int coff0 = (wn < 2) ? wn * 32 : (wn - 2) * 32;
#pragma unroll
        for (int mt = 0; mt < 4; mt++) {
#pragma unroll
            for (int h = 0; h < 2; h++) {
                int gm = m0 + wm * 64 + mt * 16 + qid + h * 8;
                if (gm < NN) {
#pragma unroll
                    for (int nt = 0; nt < 4; nt++) {
                        float2 o = make_float2(acc[mt][nt][h * 2 + 0], acc[mt][nt][h * 2 + 1]);
                        *(float2*)(dstbuf + (size_t)gm * 64 + coff0 + nt * 8 + tig * 2) = o;
                    }
                }
            }
        }
    }
}

// ---------------- final: out = norm( sum2/cnt + b2 + r2 ), 1 warp/node -----------
__global__ void k_out(const float* __restrict__ b2, float* __restrict__ out) {
    int node = (blockIdx.x * blockDim.x + threadIdx.x) >> 5;
    int lane = threadIdx.x & 31;
    if (node >= NN) return;
    float inv = g_inv[node];
    float2 s  = ((const float2*)(g_sum2 + (size_t)node * CC))[lane];
    float2 r  = ((const float2*)(g_r2   + (size_t)node * CC))[lane];
    float2 bb = ((const float2*)b2)[lane];
    float v0 = s.x * inv + bb.x + r.x;
    float v1 = s.y * inv + bb.y + r.y;
    float ss = v0 * v0 + v1 * v1;
#pragma unroll
    for (int o = 16; o >= 1; o >>= 1) ss += __shfl_xor_sync(0xffffffffu, ss, o);
    float sc = 1.0f / fmaxf(sqrtf(ss), 1e-12f);
    ((float2*)(out + (size_t)node * CC))[lane] = make_float2(v0 * sc, v1 * sc);
}

// ---------------- launch ----------------------------------------------------------
extern "C" void kernel_launch(void* const* d_in, const int* in_sizes, int n_in,
                              void* d_out, int out_size) {
    const float* x    = (const float*)d_in[0];
    const int*   ei   = (const int*)  d_in[1];
    const float* W1_l = (const float*)d_in[2];
    const float* b1   = (const float*)d_in[3];
    const float* W1_r = (const float*)d_in[4];
    const float* Wl1  = (const float*)d_in[5];
    const float* bl1  = (const float*)d_in[6];
    const float* W2_l = (const float*)d_in[7];
    const float* b2   = (const float*)d_in[8];
    const float* W2_r = (const float*)d_in[9];
    float* out = (float*)d_out;

    k_init   <<<(NN * FIN + 255) / 256, 256>>>();
    k_count  <<<(EE + 255) / 256, 256>>>(ei);
    k_invcnt <<<(NN + 255) / 256, 256>>>();
    k_scatter1<<<(EE * 32 + 255) / 256, 256>>>(ei, x);
    k_gemm<0><<<(NN + 127) / 128, 256>>>(x, W1_l, W1_r, b1);
    k_gemm<1><<<(NN + 127) / 128, 256>>>(x, Wl1, (const float*)nullptr, bl1);
    k_gemm<2><<<(NN + 127) / 128, 256>>>((const float*)nullptr, W2_l, W2_r, (const float*)nullptr);
    k_scatter2<<<(EE * 16 + 255) / 256, 256>>>(ei);
    k_out<<<(NN * 32 + 255) / 256, 256>>>(b2, out);
}

// round 3
// speedup vs baseline: 1.4246x; 1.0635x over previous
#include <cuda_runtime.h>
#include <math.h>

// Problem constants (fixed by the dataset)
#define NN  50000
#define EE  800000
#define FIN 128
#define HH  128
#define CC  64

// ---------------- device scratch ------------------------------------------------
__device__ int   g_icnt[NN];        // in-degree
__device__ int   g_rowp[NN + 1];    // CSR row offsets (by dst)
__device__ int   g_cur [NN];        // bin cursors
__device__ int   g_srcs[EE];        // src node ids sorted by dst
__device__ float g_agg [NN * FIN];  // mean_aggr(x)       (layer 1)
__device__ float g_h   [NN * HH];   // relu(norm(sage1))
__device__ float g_h2  [NN * HH];   // relu([x,h] @ Wl1^T + bl1)
__device__ float g_t2  [NN * CC];   // h2 @ W2_l^T  (pre-transformed; mean commutes)
__device__ float g_r2  [NN * CC];   // h2 @ W2_r^T
__device__ float g_agg2[NN * CC];   // mean_aggr(t2)      (layer 2)

// ---------------- degree count ----------------------------------------------------
__global__ void k_zero() {
    int i = blockIdx.x * blockDim.x + threadIdx.x;
    if (i < NN) g_icnt[i] = 0;
}

__global__ void k_count(const int* __restrict__ ei) {
    int e = blockIdx.x * blockDim.x + threadIdx.x;
    if (e < EE) atomicAdd(&g_icnt[ei[EE + e]], 1);
}

// ---------------- single-block 2-level exclusive scan ------------------------------
__global__ __launch_bounds__(1024) void k_scan() {
    __shared__ int sm[1024];
    const int t  = threadIdx.x;
    const int CH = (NN + 1023) / 1024;
    int beg = t * CH;
    int end = min(beg + CH, NN);
    int s = 0;
    for (int i = beg; i < end; i++) s += g_icnt[i];
    sm[t] = s;
    __syncthreads();
#pragma unroll
    for (int o = 1; o < 1024; o <<= 1) {
        int u = (t >= o) ? sm[t - o] : 0;
        __syncthreads();
        sm[t] += u;
        __syncthreads();
    }
    int run = sm[t] - s;   // exclusive prefix for this chunk
    for (int i = beg; i < end; i++) {
        g_rowp[i] = run;
        g_cur[i]  = run;
        run += g_icnt[i];
    }
    if (t == 1023) g_rowp[NN] = EE;
}

// ---------------- bin: srcs sorted by dst ------------------------------------------
__global__ void k_bin(const int* __restrict__ ei) {
    int e = blockIdx.x * blockDim.x + threadIdx.x;
    if (e >= EE) return;
    int src = ei[e];
    int dst = ei[EE + e];
    int p = atomicAdd(&g_cur[dst], 1);
    g_srcs[p] = src;
}

// ---------------- layer-1 mean aggregation: warp per node, 128 floats --------------
__global__ void k_aggr1(const float* __restrict__ x) {
    int node = (blockIdx.x * blockDim.x + threadIdx.x) >> 5;
    int lane = threadIdx.x & 31;
    if (node >= NN) return;
    int beg = g_rowp[node], end = g_rowp[node + 1];
    float4 acc = make_float4(0.f, 0.f, 0.f, 0.f);
    for (int i = beg; i < end; i++) {
        int s = __ldg(&g_srcs[i]);
        float4 v = ((const float4*)(x + (size_t)s * FIN))[lane];
        acc.x += v.x; acc.y += v.y; acc.z += v.z; acc.w += v.w;
    }
    float inv = 1.0f / fmaxf((float)(end - beg), 1.0f);
    acc.x *= inv; acc.y *= inv; acc.z *= inv; acc.w *= inv;
    ((float4*)(g_agg + (size_t)node * FIN))[lane] = acc;
}

// ---------------- layer-2 mean aggregation: warp per node, 64 floats ---------------
__global__ void k_aggr2() {
    int node = (blockIdx.x * blockDim.x + threadIdx.x) >> 5;
    int lane = threadIdx.x & 31;
    if (node >= NN) return;
    int beg = g_rowp[node], end = g_rowp[node + 1];
    float2 acc = make_float2(0.f, 0.f);
    for (int i = beg; i < end; i++) {
        int s = __ldg(&g_srcs[i]);
        float2 v = ((const float2*)(g_t2 + (size_t)s * CC))[lane];
        acc.x += v.x; acc.y += v.y;
    }
    float inv = 1.0f / fmaxf((float)(end - beg), 1.0f);
    acc.x *= inv; acc.y *= inv;
    ((float2*)(g_agg2 + (size_t)node * CC))[lane] = acc;
}

// ---------------- tf32 helpers ----------------------------------------------------
__device__ __forceinline__ unsigned f2tf32(float f) {
    unsigned r;
    asm("cvt.rna.tf32.f32 %0, %1;" : "=r"(r) : "f"(f));
    return r;
}

#define MMA_TF32(d, a, b)                                                       \
    asm volatile("mma.sync.aligned.m16n8k8.row.col.f32.tf32.tf32.f32 "          \
                 "{%0,%1,%2,%3}, {%4,%5,%6,%7}, {%8,%9}, {%0,%1,%2,%3};"        \
                 : "+f"(d[0]), "+f"(d[1]), "+f"(d[2]), "+f"(d[3])               \
                 : "r"(a[0]), "r"(a[1]), "r"(a[2]), "r"(a[3]),                  \
                   "r"(b[0]), "r"(b[1]))

// ---------------- tensor-core tf32 SGEMM, 128x128 tile, 8 warps ------------------
// MODE 0: g_h  = relu( norm( [agg | x] @ [W1_l|W1_r]^T + b1 ) )   K=256
// MODE 1: g_h2 = relu( [x | h] @ Wl1^T + bl1 )                    K=256
// MODE 2: [g_t2|g_r2] = g_h2 @ [W2_l ; W2_r]^T                    K=128
#define SAS 136   // smem row stride (words); 136 % 32 == 8 -> conflict-free frags

template <int MODE>
__launch_bounds__(256)
__global__ void k_gemm(const float* __restrict__ X,
                       const float* __restrict__ WA,
                       const float* __restrict__ WB,
                       const float* __restrict__ bias) {
    constexpr int KTOT = (MODE == 2) ? 128 : 256;
    __shared__ unsigned As[32 * SAS];
    __shared__ unsigned Ws[32 * SAS];
    __shared__ float    rss[128 * 4];

    const int tid  = threadIdx.x;
    const int lane = tid & 31;
    const int w    = tid >> 5;
    const int wm   = w & 1;        // 0..1 (64 rows each)
    const int wn   = w >> 1;       // 0..3 (32 cols each)
    const int qid  = lane >> 2;    // 0..7
    const int tig  = lane & 3;     // 0..3
    const int m0   = blockIdx.x * 128;

    float acc[4][4][4];
#pragma unroll
    for (int mt = 0; mt < 4; mt++)
#pragma unroll
        for (int nt = 0; nt < 4; nt++)
#pragma unroll
            for (int c = 0; c < 4; c++) acc[mt][nt][c] = 0.f;

    for (int k0 = 0; k0 < KTOT; k0 += 32) {
        // ---- A tile: 128 rows x 32 k, k-major ----
#pragma unroll
        for (int p = 0; p < 4; p++) {
            int f4 = tid + p * 256;
            int n  = f4 >> 3;
            int kq = f4 & 7;
            int k  = k0 + kq * 4;
            int gm = m0 + n;
            float4 v = make_float4(0.f, 0.f, 0.f, 0.f);
            if (gm < NN) {
                if (MODE == 0) {
                    if (k < 128) v = *(const float4*)(g_agg + (size_t)gm * 128 + k);
                    else         v = *(const float4*)(X     + (size_t)gm * 128 + (k - 128));
                } else if (MODE == 1) {
                    if (k < 128) v = *(const float4*)(X   + (size_t)gm * 128 + k);
                    else         v = *(const float4*)(g_h + (size_t)gm * 128 + (k - 128));
                } else {
                    v = *(const float4*)(g_h2 + (size_t)gm * 128 + k);
                }
            }
            int kk = kq * 4;
            As[(kk + 0) * SAS + n] = f2tf32(v.x);
            As[(kk + 1) * SAS + n] = f2tf32(v.y);
            As[(kk + 2) * SAS + n] = f2tf32(v.z);
            As[(kk + 3) * SAS + n] = f2tf32(v.w);
        }
        // ---- W tile ----
#pragma unroll
        for (int p = 0; p < 4; p++) {
            int f4 = tid + p * 256;
            int j  = f4 >> 3;
            int kq = f4 & 7;
            int k  = k0 + kq * 4;
            float4 v;
            if (MODE == 0) {
                v = (k < 128) ? *(const float4*)(WA + j * 128 + k)
                              : *(const float4*)(WB + j * 128 + (k - 128));
            } else if (MODE == 1) {
                v = *(const float4*)(WA + j * 256 + k);
            } else {
                v = (j < 64) ? *(const float4*)(WA + j * 128 + k)
                             : *(const float4*)(WB + (j - 64) * 128 + k);
            }
            int kk = kq * 4;
            Ws[(kk + 0) * SAS + j] = f2tf32(v.x);
            Ws[(kk + 1) * SAS + j] = f2tf32(v.y);
            Ws[(kk + 2) * SAS + j] = f2tf32(v.z);
            Ws[(kk + 3) * SAS + j] = f2tf32(v.w);
        }
        __syncthreads();

#pragma unroll
        for (int ks = 0; ks < 4; ks++) {
            const int kr = ks * 8 + tig;
            unsigned a[4][4];
#pragma unroll
            for (int mt = 0; mt < 4; mt++) {
                int r0 = wm * 64 + mt * 16 + qid;
                a[mt][0] = As[kr * SAS + r0];
                a[mt][1] = As[kr * SAS + r0 + 8];
                a[mt][2] = As[(kr + 4) * SAS + r0];
                a[mt][3] = As[(kr + 4) * SAS + r0 + 8];
            }
            unsigned b[4][2];
#pragma unroll
            for (int nt = 0; nt < 4; nt++) {
                int c0 = wn * 32 + nt * 8 + qid;
                b[nt][0] = Ws[kr * SAS + c0];
                b[nt][1] = Ws[(kr + 4) * SAS + c0];
            }
#pragma unroll
            for (int mt = 0; mt < 4; mt++)
#pragma unroll
                for (int nt = 0; nt < 4; nt++)
                    MMA_TF32(acc[mt][nt], a[mt], b[nt]);
        }
        __syncthreads();
    }

    // ---------------- epilogue ----------------
    if (MODE == 0 || MODE == 1) {
#pragma unroll
        for (int nt = 0; nt < 4; nt++) {
            float2 bv = *(const float2*)(bias + wn * 32 + nt * 8 + tig * 2);
#pragma unroll
            for (int mt = 0; mt < 4; mt++) {
                acc[mt][nt][0] += bv.x; acc[mt][nt][1] += bv.y;
                acc[mt][nt][2] += bv.x; acc[mt][nt][3] += bv.y;
            }
        }
    }

    if (MODE == 0) {
        float ssl[4][2];
#pragma unroll
        for (int mt = 0; mt < 4; mt++) {
            float s0 = 0.f, s1 = 0.f;
#pragma unroll
            for (int nt = 0; nt < 4; nt++) {
                s0 += acc[mt][nt][0] * acc[mt][nt][0] + acc[mt][nt][1] * acc[mt][nt][1];
                s1 += acc[mt][nt][2] * acc[mt][nt][2] + acc[mt][nt][3] * acc[mt][nt][3];
            }
            s0 += __shfl_xor_sync(0xffffffffu, s0, 1);
            s0 += __shfl_xor_sync(0xffffffffu, s0, 2);
            s1 += __shfl_xor_sync(0xffffffffu, s1, 1);
            s1 += __shfl_xor_sync(0xffffffffu, s1, 2);
            ssl[mt][0] = s0; ssl[mt][1] = s1;
        }
        if (tig == 0) {
#pragma unroll
            for (int mt = 0; mt < 4; mt++) {
                int r0 = wm * 64 + mt * 16 + qid;
                rss[(r0)     * 4 + wn] = ssl[mt][0];
                rss[(r0 + 8) * 4 + wn] = ssl[mt][1];
            }
        }
        __syncthreads();
#pragma unroll
        for (int mt = 0; mt < 4; mt++) {
#pragma unroll
            for (int h = 0; h < 2; h++) {
                int r = wm * 64 + mt * 16 + qid + h * 8;
                float ss = rss[r * 4 + 0] + rss[r * 4 + 1] + rss[r * 4 + 2] + rss[r * 4 + 3];
                float sc = 1.0f / fmaxf(sqrtf(ss), 1e-12f);
                int gm = m0 + r;
                if (gm < NN) {
#pragma unroll
                    for (int nt = 0; nt < 4; nt++) {
                        float2 o;
                        o.x = fmaxf(acc[mt][nt][h * 2 + 0] * sc, 0.f);
                        o.y = fmaxf(acc[mt][nt][h * 2 + 1] * sc, 0.f);
                        *(float2*)(g_h + (size_t)gm * 128 + wn * 32 + nt * 8 + tig * 2) = o;
                    }
                }
            }
        }
    } else if (MODE == 1) {
#pragma unroll
        for (int mt = 0; mt < 4; mt++) {
#pragma unroll
            for (int h = 0; h < 2; h++) {
                int gm = m0 + wm * 64 + mt * 16 + qid + h * 8;
                if (gm < NN) {
#pragma unroll
                    for (int nt = 0; nt < 4; nt++) {
                        float2 o;
                        o.x = fmaxf(acc[mt][nt][h * 2 + 0], 0.f);
                        o.y = fmaxf(acc[mt][nt][h * 2 + 1], 0.f);
                        *(float2*)(g_h2 + (size_t)gm * 128 + wn * 32 + nt * 8 + tig * 2) = o;
                    }
                }
            }
        }
    } else {
        float* dstbuf = (wn < 2) ? g_t2 : g_r2;
        int coff0 = (wn < 2) ? wn * 32 : (wn - 2) * 32;
#pragma unroll
        for (int mt = 0; mt < 4; mt++) {
#pragma unroll
            for (int h = 0; h < 2; h++) {
                int gm = m0 + wm * 64 + mt * 16 + qid + h * 8;
                if (gm < NN) {
#pragma unroll
                    for (int nt = 0; nt < 4; nt++) {
                        float2 o = make_float2(acc[mt][nt][h * 2 + 0], acc[mt][nt][h * 2 + 1]);
                        *(float2*)(dstbuf + (size_t)gm * 64 + coff0 + nt * 8 + tig * 2) = o;
                    }
                }
            }
        }
    }
}

// ---------------- final: out = norm( agg2 + b2 + r2 ), 1 warp/node -----------------
__global__ void k_out(const float* __restrict__ b2, float* __restrict__ out) {
    int node = (blockIdx.x * blockDim.x + threadIdx.x) >> 5;
    int lane = threadIdx.x & 31;
    if (node >= NN) return;
    float2 s  = ((const float2*)(g_agg2 + (size_t)node * CC))[lane];
    float2 r  = ((const float2*)(g_r2   + (size_t)node * CC))[lane];
    float2 bb = ((const float2*)b2)[lane];
    float v0 = s.x + bb.x + r.x;
    float v1 = s.y + bb.y + r.y;
    float ss = v0 * v0 + v1 * v1;
#pragma unroll
    for (int o = 16; o >= 1; o >>= 1) ss += __shfl_xor_sync(0xffffffffu, ss, o);
    float sc = 1.0f / fmaxf(sqrtf(ss), 1e-12f);
    ((float2*)(out + (size_t)node * CC))[lane] = make_float2(v0 * sc, v1 * sc);
}

// ---------------- launch ------------------------------------------------------------
extern "C" void kernel_launch(void* const* d_in, const int* in_sizes, int n_in,
                              void* d_out, int out_size) {
    const float* x    = (const float*)d_in[0];
    const int*   ei   = (const int*)  d_in[1];
    const float* W1_l = (const float*)d_in[2];
    const float* b1   = (const float*)d_in[3];
    const float* W1_r = (const float*)d_in[4];
    const float* Wl1  = (const float*)d_in[5];
    const float* bl1  = (const float*)d_in[6];
    const float* W2_l = (const float*)d_in[7];
    const float* b2   = (const float*)d_in[8];
    const float* W2_r = (const float*)d_in[9];
    float* out = (float*)d_out;

    k_zero  <<<(NN + 255) / 256, 256>>>();
    k_count <<<(EE + 255) / 256, 256>>>(ei);
    k_scan  <<<1, 1024>>>();
    k_bin   <<<(EE + 255) / 256, 256>>>(ei);
    k_aggr1 <<<(NN * 32 + 255) / 256, 256>>>(x);
    k_gemm<0><<<(NN + 127) / 128, 256>>>(x, W1_l, W1_r, b1);
    k_gemm<1><<<(NN + 127) / 128, 256>>>(x, Wl1, (const float*)nullptr, bl1);
    k_gemm<2><<<(NN + 127) / 128, 256>>>((const float*)nullptr, W2_l, W2_r, (const float*)nullptr);
    k_aggr2 <<<(NN * 32 + 255) / 256, 256>>>();
    k_out   <<<(NN * 32 + 255) / 256, 256>>>(b2, out);
}